// round 15
// baseline (speedup 1.0000x reference)
// =============================================================================
// Round 15 theory (comments only, ASCII).
//
// Post-mortem R14: tripped at exactly 128 MiB. R13/R14 both bundled THREE
// changes vs the passing R12 (new 32 MiB g_xtf global + new cvtx kernel +
// in-place B rounding block) and both tripped ~126-128 MiB, so the gremlin
// is NOT isolated. Updated empirical table for the CURRENT environment:
//   delta=0 passes: R12 (globals 64.3 MiB)
//   trips:          R13/R14 (globals 96.3 MiB, delta 126-128 MiB)
//                   R10 (globals 160 MiB, delta 254 MiB)
//                   R6-R9 (globals 208-352 MiB, delta 254-384 MiB)
// Monotone in globals: in this environment the mem checkpoint appears to
// charge lazily-materialized module globals (plus overhead), and only the
// <=64 MiB configuration has ever passed post-R5. Discipline: hold globals
// at R12's exact 64.3 MiB and change ONE variable.
//
// This round = R12 VERBATIM + exactly one change: in-place tf32 rounding of
// the B tile in smem (each thread rounds the 8 floats it itself cp.async'd,
// after wait_group, before syncthreads; 2x LDS.128 + 8 cvt + 2x STS.128,
// straight-line, no arrays). B fragment loads in the mainloop become plain
// LDS. This removes the 4x-redundant B cvts (each B element was re-rounded
// by all 4 warp-rows): -32 cvt per thread per 32-K iteration, ~20% of the
// mainloop issue count. Numerics bit-identical (same rounding points).
// A-side stays R12 (in-register cvt for stage 1, H2F for stage 2); no new
// globals, no new kernels.
//
// Prediction: PASS, delta=0 (globals byte-identical to the R12 pass; the
// only new code is straight-line), rel_err ~4.2e-4 (bit-identical),
// dur_us 1446 -> ~1250-1330. Post-mortem value: if it TRIPS, the rounding
// block itself is the allocator trigger (fully isolated), and next round
// reverts it and instead widens the warp tile for LDS-per-MMA reduction.
// =============================================================================
#include <cuda_runtime.h>
#include <cuda_fp16.h>
#include <math.h>
#include <stdint.h>

#define NTOK   8192
#define DDIM   1024
#define NEXP   8
#define HDIM   2048
#define NPAIR  (NTOK * 2)

#define OUT_OFF   ((size_t)0)
#define OUT_SZ    ((size_t)NTOK * DDIM)
#define AUX_OFF   (OUT_OFF + OUT_SZ)
#define PROBS_OFF (AUX_OFF + 1)
#define IDX_OFF   (PROBS_OFF + (size_t)NTOK * NEXP)
#define TP_OFF    (IDX_OFF + (size_t)NTOK * 2)

// ---- device scratch: 64.3 MiB total (identical to the R12 pass) ----
__device__ __half g_h[(size_t)NPAIR * HDIM];   // 64 MiB, expert-sorted hidden
__device__ int    g_list[NEXP * NTOK];         // pid = tok*2+slot per expert
__device__ int    g_count[NEXP];
__device__ int    g_off[NEXP];
__device__ float  g_probsum[NEXP];

__device__ __forceinline__ float gelu_exact(float v) {
    return 0.5f * v * (1.0f + erff(v * 0.70710678118654752f));
}
__device__ __forceinline__ uint32_t tf32u(float v) {
    uint32_t r;
    asm("cvt.rna.tf32.f32 %0, %1;" : "=r"(r) : "f"(v));
    return r;
}
__device__ __forceinline__ float tf32f(float v) {
    uint32_t r;
    asm("cvt.rna.tf32.f32 %0, %1;" : "=r"(r) : "f"(v));
    return __uint_as_float(r);
}
__device__ __forceinline__ uint32_t s2u(const void* p) {
    uint32_t a;
    asm("{ .reg .u64 t; cvta.to.shared.u64 t, %1; cvt.u32.u64 %0, t; }"
        : "=r"(a) : "l"(p));
    return a;
}
__device__ __forceinline__ void cpa16(uint32_t dst, const void* src) {
    asm volatile("cp.async.cg.shared.global [%0], [%1], 16;"
                 :: "r"(dst), "l"(src) : "memory");
}
__device__ __forceinline__ void mma_tf32(
    float& c0, float& c1, float& c2, float& c3,
    uint32_t a0, uint32_t a1, uint32_t a2, uint32_t a3,
    uint32_t b0, uint32_t b1)
{
    asm volatile(
        "mma.sync.aligned.m16n8k8.row.col.f32.tf32.tf32.f32 "
        "{%0,%1,%2,%3}, {%4,%5,%6,%7}, {%8,%9}, {%0,%1,%2,%3};"
        : "+f"(c0), "+f"(c1), "+f"(c2), "+f"(c3)
        : "r"(a0), "r"(a1), "r"(a2), "r"(a3), "r"(b0), "r"(b1));
}

__global__ void zero_kernel() {
    int t = threadIdx.x;
    if (t < NEXP) { g_count[t] = 0; g_probsum[t] = 0.f; }
}

__global__ __launch_bounds__(256) void zero_out_kernel(float* __restrict__ out) {
    size_t i = (size_t)blockIdx.x * blockDim.x + threadIdx.x;
    if (i < OUT_SZ / 4)
        ((float4*)(out + OUT_OFF))[i] = make_float4(0.f, 0.f, 0.f, 0.f);
}

__global__ void scan_kernel() {
    if (threadIdx.x == 0) {
        int a = 0;
        for (int e = 0; e < NEXP; e++) { g_off[e] = a; a += g_count[e]; }
    }
}

__global__ __launch_bounds__(256) void router_kernel(
    const float* __restrict__ x, const float* __restrict__ gw,
    float* __restrict__ out)
{
    __shared__ float sprob[NEXP];
    int tid = threadIdx.x;
    if (tid < NEXP) sprob[tid] = 0.f;
    __syncthreads();

    int tok  = (blockIdx.x * blockDim.x + tid) >> 5;
    int lane = tid & 31;

    if (tok < NTOK) {
        const float* xr = x + (size_t)tok * DDIM;
        float acc[NEXP];
#pragma unroll
        for (int e = 0; e < NEXP; e++) acc[e] = 0.f;
        for (int d = lane; d < DDIM; d += 32) {
            float xv = xr[d];
            const float* g = gw + (size_t)d * NEXP;
#pragma unroll
            for (int e = 0; e < NEXP; e++) acc[e] += xv * g[e];
        }
#pragma unroll
        for (int off = 16; off > 0; off >>= 1)
#pragma unroll
            for (int e = 0; e < NEXP; e++)
                acc[e] += __shfl_down_sync(0xffffffffu, acc[e], off);

        if (lane == 0) {
            float mx = acc[0];
#pragma unroll
            for (int e = 1; e < NEXP; e++) mx = fmaxf(mx, acc[e]);
            float p[NEXP], s = 0.f;
#pragma unroll
            for (int e = 0; e < NEXP; e++) { p[e] = __expf(acc[e] - mx); s += p[e]; }
            float inv = 1.f / s;
#pragma unroll
            for (int e = 0; e < NEXP; e++) {
                p[e] *= inv;
                out[PROBS_OFF + (size_t)tok * NEXP + e] = p[e];
                atomicAdd(&sprob[e], p[e]);
            }
            int i0 = 0;
#pragma unroll
            for (int e = 1; e < NEXP; e++) if (p[e] > p[i0]) i0 = e;
            int i1 = -1;
#pragma unroll
            for (int e = 0; e < NEXP; e++)
                if (e != i0 && (i1 < 0 || p[e] > p[i1])) i1 = e;
            float ps  = p[i0] + p[i1];
            out[IDX_OFF + (size_t)tok * 2 + 0] = (float)i0;
            out[IDX_OFF + (size_t)tok * 2 + 1] = (float)i1;
            out[TP_OFF  + (size_t)tok * 2 + 0] = p[i0] / ps;
            out[TP_OFF  + (size_t)tok * 2 + 1] = p[i1] / ps;
            int pos0 = atomicAdd(&g_count[i0], 1);
            g_list[i0 * NTOK + pos0] = tok * 2 + 0;
            int pos1 = atomicAdd(&g_count[i1], 1);
            g_list[i1 * NTOK + pos1] = tok * 2 + 1;
        }
    }
    __syncthreads();
    if (tid < NEXP) atomicAdd(&g_probsum[tid], sprob[tid]);
}

// Grouped GEMM, tf32 mma.sync, CTA 128(M) x 64(N) x 32(K), 8 warps (4x2),
// warp tile 32x32 (acc[2][4][4]). Double-buffered cp.async, 2-element stage
// arrays indexed by (it & 1) only. B tiles from UNtransposed weights,
// tf32-rounded IN PLACE in smem by the loading thread (the one change vs
// the R12 pass). A side identical to R12.
// STAGE 1: A = x rows gathered (cvt in-register), B = w1[e] -> g_h fp16
// STAGE 2: A = g_h sorted (fp16, exact in tf32), B = w2[e] -> atomicAdd out
#define BK    32
#define LDA1  36                        // floats
#define LDA2  40                        // halves
#define LDB   72                        // floats
#define ATB1  (128 * LDA1 * 4)          // 18432 bytes
#define ATB2  (128 * LDA2 * 2)          // 10240 bytes
#define BTB   (BK * LDB * 4)            // 9216 bytes
#define DYN1  (2 * (ATB1 + BTB))        // 55296 bytes
#define DYN2  (2 * (ATB2 + BTB))        // 38912 bytes

template <int STAGE>
__global__ __launch_bounds__(256) void mma_gemm(
    const float* __restrict__ Xf, const float* __restrict__ W,
    float* __restrict__ out)
{
    constexpr int KD   = (STAGE == 1) ? DDIM : HDIM;
    constexpr int ND   = (STAGE == 1) ? HDIM : DDIM;
    constexpr int NIT  = KD / BK;
    constexpr int ATB  = (STAGE == 1) ? ATB1 : ATB2;

    int e    = blockIdx.z;
    int cnt  = g_count[e];
    int row0 = blockIdx.y * 128;
    if (row0 >= cnt) return;
    int col0 = blockIdx.x * 64;
    int base = g_off[e];

    extern __shared__ __align__(16) char dyn[];
    uint32_t sb = s2u(dyn);
    // layout: A0 | A1 | B0 | B1
    uint32_t aS[2] = { sb, sb + ATB };
    uint32_t bS[2] = { sb + 2u * ATB, sb + 2u * ATB + BTB };

    int tid  = threadIdx.x;
    int wid  = tid >> 5;
    int lane = tid & 31;
    int g    = lane >> 2;
    int tg   = lane & 3;
    int wm   = (wid >> 1) * 32;   // 4 warp-rows cover M=128
    int wn   = (wid & 1) * 32;    // 2 warp-cols cover N=64

    // ---- load roles ----
    int lrow = tid >> 1;               // 0..127 (A row)
    const float*  arowF = nullptr;
    const __half* arowH = nullptr;
    if (STAGE == 1) {
        int m = row0 + lrow;
        int pid = (m < cnt) ? g_list[e * NTOK + m] : g_list[e * NTOK];
        arowF = Xf + (size_t)(pid >> 1) * DDIM + (tid & 1) * 16;
    } else {
        int m = row0 + lrow;
        size_t r = (m < cnt) ? (size_t)(base + m) : (size_t)base;
        arowH = g_h + r * HDIM + (tid & 1) * 16;
    }
    uint32_t aOff = (STAGE == 1)
        ? (uint32_t)(lrow * LDA1 + (tid & 1) * 16) * 4
        : (uint32_t)(lrow * LDA2 + (tid & 1) * 16) * 2;

    const float* wb = W + (size_t)e * DDIM * HDIM;
    int br0 = tid >> 4,         bc0 = (tid & 15) * 4;
    int br1 = (tid + 256) >> 4, bc1 = ((tid + 256) & 15) * 4;
    uint32_t bOff0 = (uint32_t)(br0 * LDB + bc0) * 4;
    uint32_t bOff1 = (uint32_t)(br1 * LDB + bc1) * 4;

    float acc[2][4][4];
#pragma unroll
    for (int i = 0; i < 2; i++)
#pragma unroll
        for (int j = 0; j < 4; j++)
#pragma unroll
            for (int c = 0; c < 4; c++) acc[i][j][c] = 0.f;

    // ---- prologue: k-tile 0 into buffer 0 ----
    if (STAGE == 1) {
#pragma unroll
        for (int j = 0; j < 4; j++)
            cpa16(aS[0] + aOff + j * 16, arowF + j * 4);
    } else {
#pragma unroll
        for (int j = 0; j < 2; j++)
            cpa16(aS[0] + aOff + j * 16, arowH + j * 8);
    }
    cpa16(bS[0] + bOff0, wb + (size_t)br0 * ND + col0 + bc0);
    cpa16(bS[0] + bOff1, wb + (size_t)br1 * ND + col0 + bc1);
    asm volatile("cp.async.commit_group;" ::: "memory");

    for (int it = 0; it < NIT; it++) {
        int b = it & 1;
        if (it + 1 < NIT) {
            int nb = b ^ 1;
            int kt = (it + 1) * BK;
            if (STAGE == 1) {
#pragma unroll
                for (int j = 0; j < 4; j++)
                    cpa16(aS[nb] + aOff + j * 16, arowF + kt + j * 4);
            } else {
#pragma unroll
                for (int j = 0; j < 2; j++)
                    cpa16(aS[nb] + aOff + j * 16, arowH + kt + j * 8);
            }
            cpa16(bS[nb] + bOff0, wb + (size_t)(kt + br0) * ND + col0 + bc0);
            cpa16(bS[nb] + bOff1, wb + (size_t)(kt + br1) * ND + col0 + bc1);
            asm volatile("cp.async.commit_group;" ::: "memory");
            asm volatile("cp.async.wait_group 1;" ::: "memory");
        } else {
            asm volatile("cp.async.wait_group 0;" ::: "memory");
        }

        // THE ONE CHANGE vs R12: in-place tf32 rounding of this thread's OWN
        // B chunks (visible to this thread after wait_group; syncthreads
        // publishes the rounded values to the CTA). Straight-line code.
        {
            float4* p0 = (float4*)(dyn + 2 * ATB + (size_t)b * BTB + bOff0);
            float4 v0 = *p0;
            v0.x = tf32f(v0.x); v0.y = tf32f(v0.y);
            v0.z = tf32f(v0.z); v0.w = tf32f(v0.w);
            *p0 = v0;
            float4* p1 = (float4*)(dyn + 2 * ATB + (size_t)b * BTB + bOff1);
            float4 v1 = *p1;
            v1.x = tf32f(v1.x); v1.y = tf32f(v1.y);
            v1.z = tf32f(v1.z); v1.w = tf32f(v1.w);
            *p1 = v1;
        }
        __syncthreads();

        const float*  AtF = (const float*)(dyn + (size_t)b * ATB);
        const __half* AtH = (const __half*)(dyn + (size_t)b * ATB);
        const float*  Bt  = (const float*)(dyn + 2 * ATB + (size_t)b * BTB);

#pragma unroll
        for (int kk = 0; kk < BK; kk += 8) {
            uint32_t bf[4][2];
#pragma unroll
            for (int ni = 0; ni < 4; ni++) {
                const float* bp = Bt + (kk + tg) * LDB + wn + ni * 8 + g;
                bf[ni][0] = __float_as_uint(bp[0]);
                bf[ni][1] = __float_as_uint(bp[4 * LDB]);
            }
#pragma unroll
            for (int mi = 0; mi < 2; mi++) {
                uint32_t a0, a1, a2, a3;
                if (STAGE == 1) {
                    const float* ap = AtF + (wm + mi * 16 + g) * LDA1 + kk + tg;
                    a0 = tf32u(ap[0]);
                    a1 = tf32u(ap[8 * LDA1]);
                    a2 = tf32u(ap[4]);
                    a3 = tf32u(ap[8 * LDA1 + 4]);
                } else {
                    // fp16 values are exactly tf32-representable
                    const __half* ap = AtH + (wm + mi * 16 + g) * LDA2 + kk + tg;
                    a0 = __float_as_uint(__half2float(ap[0]));
                    a1 = __float_as_uint(__half2float(ap[8 * LDA2]));
                    a2 = __float_as_uint(__half2float(ap[4]));
                    a3 = __float_as_uint(__half2float(ap[8 * LDA2 + 4]));
                }
#pragma unroll
                for (int ni = 0; ni < 4; ni++)
                    mma_tf32(acc[mi][ni][0], acc[mi][ni][1],
                             acc[mi][ni][2], acc[mi][ni][3],
                             a0, a1, a2, a3, bf[ni][0], bf[ni][1]);
            }
        }
        __syncthreads();
    }

    // ---- epilogue ----
#pragma unroll
    for (int mi = 0; mi < 2; mi++) {
        int r0 = wm + mi * 16 + g;
        int r1 = r0 + 8;
        bool ok0 = (row0 + r0) < cnt;
        bool ok1 = (row0 + r1) < cnt;
        if (STAGE == 1) {
            __half* p0 = g_h + (size_t)(base + row0 + r0) * HDIM + col0;
            __half* p1 = g_h + (size_t)(base + row0 + r1) * HDIM + col0;
#pragma unroll
            for (int ni = 0; ni < 4; ni++) {
                int c = wn + ni * 8 + tg * 2;
                if (ok0) *(__half2*)(p0 + c) = __floats2half2_rn(
                    gelu_exact(acc[mi][ni][0]), gelu_exact(acc[mi][ni][1]));
                if (ok1) *(__half2*)(p1 + c) = __floats2half2_rn(
                    gelu_exact(acc[mi][ni][2]), gelu_exact(acc[mi][ni][3]));
            }
        } else {
            int pid0 = ok0 ? g_list[e * NTOK + row0 + r0] : 0;
            int pid1 = ok1 ? g_list[e * NTOK + row0 + r1] : 0;
            float w0v = ok0 ? out[TP_OFF + pid0] : 0.f;
            float w1v = ok1 ? out[TP_OFF + pid1] : 0.f;
            float* o0 = out + OUT_OFF + (size_t)(pid0 >> 1) * DDIM + col0;
            float* o1 = out + OUT_OFF + (size_t)(pid1 >> 1) * DDIM + col0;
#pragma unroll
            for (int ni = 0; ni < 4; ni++) {
                int c = wn + ni * 8 + tg * 2;
                if (ok0) {
                    atomicAdd(o0 + c,     w0v * acc[mi][ni][0]);
                    atomicAdd(o0 + c + 1, w0v * acc[mi][ni][1]);
                }
                if (ok1) {
                    atomicAdd(o1 + c,     w1v * acc[mi][ni][2]);
                    atomicAdd(o1 + c + 1, w1v * acc[mi][ni][3]);
                }
            }
        }
    }
}

__global__ void aux_kernel(float* __restrict__ out) {
    if (threadIdx.x == 0) {
        float s = 0.f;
#pragma unroll
        for (int e = 0; e < NEXP; e++)
            s += ((float)g_count[e] / (float)NTOK) * (g_probsum[e] / (float)NTOK);
        out[AUX_OFF] = (float)NEXP * s;
    }
}

extern "C" void kernel_launch(void* const* d_in, const int* in_sizes, int n_in,
                              void* d_out, int out_size) {
    const float* x  = (const float*)d_in[0];   // [B,T,D]
    const float* gw = (const float*)d_in[1];   // [D,E]
    const float* w1 = (const float*)d_in[2];   // [E,D,H]
    const float* w2 = (const float*)d_in[3];   // [E,H,D]
    float* out = (float*)d_out;

    cudaFuncSetAttribute(mma_gemm<1>, cudaFuncAttributeMaxDynamicSharedMemorySize, DYN1);
    cudaFuncSetAttribute(mma_gemm<2>, cudaFuncAttributeMaxDynamicSharedMemorySize, DYN2);

    zero_kernel<<<1, 32>>>();
    zero_out_kernel<<<(unsigned)((OUT_SZ / 4 + 255) / 256), 256>>>(out);
    router_kernel<<<(NTOK * 32) / 256, 256>>>(x, gw, out);
    scan_kernel<<<1, 32>>>();

    mma_gemm<1><<<dim3(HDIM / 64, NTOK / 128, NEXP), 256, DYN1>>>(x, w1, out);
    mma_gemm<2><<<dim3(DDIM / 64, NTOK / 128, NEXP), 256, DYN2>>>(nullptr, w2, out);

    aux_kernel<<<1, 32>>>(out);
}

// round 16
// speedup vs baseline: 1.1658x; 1.1658x over previous
// =============================================================================
// Round 16 theory (comments only, ASCII).
//
// Post-mortem R15: PASS, delta=0, 1526us -- SLOWER than R12's 1446. The
// in-place B rounding (smem round-trip + extra sync pressure) cost more than
// the removed cvts saved -> the mainloop is NOT issue-bound at the margin,
// it is latency/ILP-bound. Also confirmed: the 64.3 MiB global footprint
// passes reproducibly (2/2). Revert the B-rounding change.
//
// This round: ONE structural change to the proven R12 skeleton -- restore
// R4's WIDER WARP TILE. CTA 128(M) x 128(N) x 32(K), 8 warps in 2x4, warp
// tile 64x32, acc[4][4][4] (the exact warp geometry that ran 735us of GEMM
// in R4). Everything else stays R12: raw untransposed B with in-register
// tf32 cvt (N-major smem [32][136], fragment word (8*tg+g) mod 32 is a
// permutation -> conflict-free), stage-1 A cvt in-register, stage-2 A fp16
// (exact in tf32), atomicAdd scatter epilogue, 64.3 MiB globals, 2-element
// stage buffers indexed by (it & 1) only.
// Why it should win: 2x MMAs per fragment-load+cvt (cvt+LDS per MMA drops
// from 2.0+... to ~1.5), half the CTAs -> half the gathered-A gmem traffic,
// and 64 MMAs in flight per iter per thread for ILP. Regs ~170 (R4 measured
// 167, passed clean); smem 70 KiB (stage1) -> 1-2 CTA/SM, same as R4.
//
// Prediction: PASS with delta=0 (globals unchanged at the passing 64.3 MiB;
// code shape matches the R4-validated register profile), rel_err ~4.2e-4,
// dur_us 1446 -> ~950-1100 (R4 GEMM 735us + ~15% cvt tax + router/zero/aux
// ~70us, minus transposes/combine that R4 paid). If it trips, the env
// cannot host >64-reg-acc kernels and next round tries 4 warps of 64x32 at
// 128 threads instead.
// =============================================================================
#include <cuda_runtime.h>
#include <cuda_fp16.h>
#include <math.h>
#include <stdint.h>

#define NTOK   8192
#define DDIM   1024
#define NEXP   8
#define HDIM   2048
#define NPAIR  (NTOK * 2)

#define OUT_OFF   ((size_t)0)
#define OUT_SZ    ((size_t)NTOK * DDIM)
#define AUX_OFF   (OUT_OFF + OUT_SZ)
#define PROBS_OFF (AUX_OFF + 1)
#define IDX_OFF   (PROBS_OFF + (size_t)NTOK * NEXP)
#define TP_OFF    (IDX_OFF + (size_t)NTOK * 2)

// ---- device scratch: 64.3 MiB total (identical to the R12/R15 passes) ----
__device__ __half g_h[(size_t)NPAIR * HDIM];   // 64 MiB, expert-sorted hidden
__device__ int    g_list[NEXP * NTOK];         // pid = tok*2+slot per expert
__device__ int    g_count[NEXP];
__device__ int    g_off[NEXP];
__device__ float  g_probsum[NEXP];

__device__ __forceinline__ float gelu_exact(float v) {
    return 0.5f * v * (1.0f + erff(v * 0.70710678118654752f));
}
__device__ __forceinline__ uint32_t tf32u(float v) {
    uint32_t r;
    asm("cvt.rna.tf32.f32 %0, %1;" : "=r"(r) : "f"(v));
    return r;
}
__device__ __forceinline__ uint32_t s2u(const void* p) {
    uint32_t a;
    asm("{ .reg .u64 t; cvta.to.shared.u64 t, %1; cvt.u32.u64 %0, t; }"
        : "=r"(a) : "l"(p));
    return a;
}
__device__ __forceinline__ void cpa16(uint32_t dst, const void* src) {
    asm volatile("cp.async.cg.shared.global [%0], [%1], 16;"
                 :: "r"(dst), "l"(src) : "memory");
}
__device__ __forceinline__ void mma_tf32(
    float& c0, float& c1, float& c2, float& c3,
    uint32_t a0, uint32_t a1, uint32_t a2, uint32_t a3,
    uint32_t b0, uint32_t b1)
{
    asm volatile(
        "mma.sync.aligned.m16n8k8.row.col.f32.tf32.tf32.f32 "
        "{%0,%1,%2,%3}, {%4,%5,%6,%7}, {%8,%9}, {%0,%1,%2,%3};"
        : "+f"(c0), "+f"(c1), "+f"(c2), "+f"(c3)
        : "r"(a0), "r"(a1), "r"(a2), "r"(a3), "r"(b0), "r"(b1));
}

__global__ void zero_kernel() {
    int t = threadIdx.x;
    if (t < NEXP) { g_count[t] = 0; g_probsum[t] = 0.f; }
}

__global__ __launch_bounds__(256) void zero_out_kernel(float* __restrict__ out) {
    size_t i = (size_t)blockIdx.x * blockDim.x + threadIdx.x;
    if (i < OUT_SZ / 4)
        ((float4*)(out + OUT_OFF))[i] = make_float4(0.f, 0.f, 0.f, 0.f);
}

__global__ void scan_kernel() {
    if (threadIdx.x == 0) {
        int a = 0;
        for (int e = 0; e < NEXP; e++) { g_off[e] = a; a += g_count[e]; }
    }
}

__global__ __launch_bounds__(256) void router_kernel(
    const float* __restrict__ x, const float* __restrict__ gw,
    float* __restrict__ out)
{
    __shared__ float sprob[NEXP];
    int tid = threadIdx.x;
    if (tid < NEXP) sprob[tid] = 0.f;
    __syncthreads();

    int tok  = (blockIdx.x * blockDim.x + tid) >> 5;
    int lane = tid & 31;

    if (tok < NTOK) {
        const float* xr = x + (size_t)tok * DDIM;
        float acc[NEXP];
#pragma unroll
        for (int e = 0; e < NEXP; e++) acc[e] = 0.f;
        for (int d = lane; d < DDIM; d += 32) {
            float xv = xr[d];
            const float* g = gw + (size_t)d * NEXP;
#pragma unroll
            for (int e = 0; e < NEXP; e++) acc[e] += xv * g[e];
        }
#pragma unroll
        for (int off = 16; off > 0; off >>= 1)
#pragma unroll
            for (int e = 0; e < NEXP; e++)
                acc[e] += __shfl_down_sync(0xffffffffu, acc[e], off);

        if (lane == 0) {
            float mx = acc[0];
#pragma unroll
            for (int e = 1; e < NEXP; e++) mx = fmaxf(mx, acc[e]);
            float p[NEXP], s = 0.f;
#pragma unroll
            for (int e = 0; e < NEXP; e++) { p[e] = __expf(acc[e] - mx); s += p[e]; }
            float inv = 1.f / s;
#pragma unroll
            for (int e = 0; e < NEXP; e++) {
                p[e] *= inv;
                out[PROBS_OFF + (size_t)tok * NEXP + e] = p[e];
                atomicAdd(&sprob[e], p[e]);
            }
            int i0 = 0;
#pragma unroll
            for (int e = 1; e < NEXP; e++) if (p[e] > p[i0]) i0 = e;
            int i1 = -1;
#pragma unroll
            for (int e = 0; e < NEXP; e++)
                if (e != i0 && (i1 < 0 || p[e] > p[i1])) i1 = e;
            float ps  = p[i0] + p[i1];
            out[IDX_OFF + (size_t)tok * 2 + 0] = (float)i0;
            out[IDX_OFF + (size_t)tok * 2 + 1] = (float)i1;
            out[TP_OFF  + (size_t)tok * 2 + 0] = p[i0] / ps;
            out[TP_OFF  + (size_t)tok * 2 + 1] = p[i1] / ps;
            int pos0 = atomicAdd(&g_count[i0], 1);
            g_list[i0 * NTOK + pos0] = tok * 2 + 0;
            int pos1 = atomicAdd(&g_count[i1], 1);
            g_list[i1 * NTOK + pos1] = tok * 2 + 1;
        }
    }
    __syncthreads();
    if (tid < NEXP) atomicAdd(&g_probsum[tid], sprob[tid]);
}

// Grouped GEMM, tf32 mma.sync, CTA 128(M) x 128(N) x 32(K), 8 warps (2x4),
// warp tile 64x32 (acc[4][4][4], R4 geometry). Double-buffered cp.async,
// 2-element stage arrays indexed by (it & 1) only. B from UNtransposed
// weights, N-major smem [32][136], tf32 cvt at fragment load.
// STAGE 1: A = x rows gathered (cvt in-register), B = w1[e] -> g_h fp16
// STAGE 2: A = g_h sorted (fp16, exact in tf32), B = w2[e] -> atomicAdd out
#define BK    32
#define LDA1  36                        // floats
#define LDA2  40                        // halves
#define LDB   136                       // floats (128 cols + pad 8)
#define ATB1  (128 * LDA1 * 4)          // 18432 bytes
#define ATB2  (128 * LDA2 * 2)          // 10240 bytes
#define BTB   (BK * LDB * 4)            // 17408 bytes
#define DYN1  (2 * (ATB1 + BTB))        // 71680 bytes
#define DYN2  (2 * (ATB2 + BTB))        // 55296 bytes

template <int STAGE>
__global__ __launch_bounds__(256) void mma_gemm(
    const float* __restrict__ Xf, const float* __restrict__ W,
    float* __restrict__ out)
{
    constexpr int KD   = (STAGE == 1) ? DDIM : HDIM;
    constexpr int ND   = (STAGE == 1) ? HDIM : DDIM;
    constexpr int NIT  = KD / BK;
    constexpr int ATB  = (STAGE == 1) ? ATB1 : ATB2;

    int e    = blockIdx.z;
    int cnt  = g_count[e];
    int row0 = blockIdx.y * 128;
    if (row0 >= cnt) return;
    int col0 = blockIdx.x * 128;
    int base = g_off[e];

    extern __shared__ __align__(16) char dyn[];
    uint32_t sb = s2u(dyn);
    // layout: A0 | A1 | B0 | B1
    uint32_t aS[2] = { sb, sb + ATB };
    uint32_t bS[2] = { sb + 2u * ATB, sb + 2u * ATB + BTB };

    int tid  = threadIdx.x;
    int wid  = tid >> 5;
    int lane = tid & 31;
    int g    = lane >> 2;
    int tg   = lane & 3;
    int wm   = (wid >> 2) * 64;   // 2 warp-rows cover M=128
    int wn   = (wid & 3) * 32;    // 4 warp-cols cover N=128

    // ---- load roles ----
    int lrow = tid >> 1;               // 0..127 (A row)
    const float*  arowF = nullptr;
    const __half* arowH = nullptr;
    if (STAGE == 1) {
        int m = row0 + lrow;
        int pid = (m < cnt) ? g_list[e * NTOK + m] : g_list[e * NTOK];
        arowF = Xf + (size_t)(pid >> 1) * DDIM + (tid & 1) * 16;
    } else {
        int m = row0 + lrow;
        size_t r = (m < cnt) ? (size_t)(base + m) : (size_t)base;
        arowH = g_h + r * HDIM + (tid & 1) * 16;
    }
    uint32_t aOff = (STAGE == 1)
        ? (uint32_t)(lrow * LDA1 + (tid & 1) * 16) * 4
        : (uint32_t)(lrow * LDA2 + (tid & 1) * 16) * 2;

    // B tile: 32 rows x 128 floats; 256 threads x 4 float4-chunks.
    // chunk role: row = (tid>>5) + j*8, col = (tid&31)*4
    const float* wb = W + (size_t)e * DDIM * HDIM;
    int brow = tid >> 5;               // 0..7
    int bcol = (tid & 31) * 4;
    uint32_t bOff = (uint32_t)(brow * LDB + bcol) * 4;

    float acc[4][4][4];
#pragma unroll
    for (int i = 0; i < 4; i++)
#pragma unroll
        for (int j = 0; j < 4; j++)
#pragma unroll
            for (int c = 0; c < 4; c++) acc[i][j][c] = 0.f;

    // ---- prologue: k-tile 0 into buffer 0 ----
    if (STAGE == 1) {
#pragma unroll
        for (int j = 0; j < 4; j++)
            cpa16(aS[0] + aOff + j * 16, arowF + j * 4);
    } else {
#pragma unroll
        for (int j = 0; j < 2; j++)
            cpa16(aS[0] + aOff + j * 16, arowH + j * 8);
    }
#pragma unroll
    for (int j = 0; j < 4; j++)
        cpa16(bS[0] + bOff + j * (8 * LDB * 4),
              wb + (size_t)(brow + j * 8) * ND + col0 + bcol);
    asm volatile("cp.async.commit_group;" ::: "memory");

    for (int it = 0; it < NIT; it++) {
        int b = it & 1;
        if (it + 1 < NIT) {
            int nb = b ^ 1;
            int kt = (it + 1) * BK;
            if (STAGE == 1) {
#pragma unroll
                for (int j = 0; j < 4; j++)
                    cpa16(aS[nb] + aOff + j * 16, arowF + kt + j * 4);
            } else {
#pragma unroll
                for (int j = 0; j < 2; j++)
                    cpa16(aS[nb] + aOff + j * 16, arowH + kt + j * 8);
            }
#pragma unroll
            for (int j = 0; j < 4; j++)
                cpa16(bS[nb] + bOff + j * (8 * LDB * 4),
                      wb + (size_t)(kt + brow + j * 8) * ND + col0 + bcol);
            asm volatile("cp.async.commit_group;" ::: "memory");
            asm volatile("cp.async.wait_group 1;" ::: "memory");
        } else {
            asm volatile("cp.async.wait_group 0;" ::: "memory");
        }
        __syncthreads();

        const float*  AtF = (const float*)(dyn + (size_t)b * ATB);
        const __half* AtH = (const __half*)(dyn + (size_t)b * ATB);
        const float*  Bt  = (const float*)(dyn + 2 * ATB + (size_t)b * BTB);

#pragma unroll
        for (int kk = 0; kk < BK; kk += 8) {
            uint32_t bf[4][2];
#pragma unroll
            for (int ni = 0; ni < 4; ni++) {
                const float* bp = Bt + (kk + tg) * LDB + wn + ni * 8 + g;
                bf[ni][0] = tf32u(bp[0]);
                bf[ni][1] = tf32u(bp[4 * LDB]);
            }
#pragma unroll
            for (int mi = 0; mi < 4; mi++) {
                uint32_t a0, a1, a2, a3;
                if (STAGE == 1) {
                    const float* ap = AtF + (wm + mi * 16 + g) * LDA1 + kk + tg;
                    a0 = tf32u(ap[0]);
                    a1 = tf32u(ap[8 * LDA1]);
                    a2 = tf32u(ap[4]);
                    a3 = tf32u(ap[8 * LDA1 + 4]);
                } else {
                    // fp16 values are exactly tf32-representable
                    const __half* ap = AtH + (wm + mi * 16 + g) * LDA2 + kk + tg;
                    a0 = __float_as_uint(__half2float(ap[0]));
                    a1 = __float_as_uint(__half2float(ap[8 * LDA2]));
                    a2 = __float_as_uint(__half2float(ap[4]));
                    a3 = __float_as_uint(__half2float(ap[8 * LDA2 + 4]));
                }
#pragma unroll
                for (int ni = 0; ni < 4; ni++)
                    mma_tf32(acc[mi][ni][0], acc[mi][ni][1],
                             acc[mi][ni][2], acc[mi][ni][3],
                             a0, a1, a2, a3, bf[ni][0], bf[ni][1]);
            }
        }
        __syncthreads();
    }

    // ---- epilogue ----
#pragma unroll
    for (int mi = 0; mi < 4; mi++) {
        int r0 = wm + mi * 16 + g;
        int r1 = r0 + 8;
        bool ok0 = (row0 + r0) < cnt;
        bool ok1 = (row0 + r1) < cnt;
        if (STAGE == 1) {
            __half* p0 = g_h + (size_t)(base + row0 + r0) * HDIM + col0;
            __half* p1 = g_h + (size_t)(base + row0 + r1) * HDIM + col0;
#pragma unroll
            for (int ni = 0; ni < 4; ni++) {
                int c = wn + ni * 8 + tg * 2;
                if (ok0) *(__half2*)(p0 + c) = __floats2half2_rn(
                    gelu_exact(acc[mi][ni][0]), gelu_exact(acc[mi][ni][1]));
                if (ok1) *(__half2*)(p1 + c) = __floats2half2_rn(
                    gelu_exact(acc[mi][ni][2]), gelu_exact(acc[mi][ni][3]));
            }
        } else {
            int pid0 = ok0 ? g_list[e * NTOK + row0 + r0] : 0;
            int pid1 = ok1 ? g_list[e * NTOK + row0 + r1] : 0;
            float w0v = ok0 ? out[TP_OFF + pid0] : 0.f;
            float w1v = ok1 ? out[TP_OFF + pid1] : 0.f;
            float* o0 = out + OUT_OFF + (size_t)(pid0 >> 1) * DDIM + col0;
            float* o1 = out + OUT_OFF + (size_t)(pid1 >> 1) * DDIM + col0;
#pragma unroll
            for (int ni = 0; ni < 4; ni++) {
                int c = wn + ni * 8 + tg * 2;
                if (ok0) {
                    atomicAdd(o0 + c,     w0v * acc[mi][ni][0]);
                    atomicAdd(o0 + c + 1, w0v * acc[mi][ni][1]);
                }
                if (ok1) {
                    atomicAdd(o1 + c,     w1v * acc[mi][ni][2]);
                    atomicAdd(o1 + c + 1, w1v * acc[mi][ni][3]);
                }
            }
        }
    }
}

__global__ void aux_kernel(float* __restrict__ out) {
    if (threadIdx.x == 0) {
        float s = 0.f;
#pragma unroll
        for (int e = 0; e < NEXP; e++)
            s += ((float)g_count[e] / (float)NTOK) * (g_probsum[e] / (float)NTOK);
        out[AUX_OFF] = (float)NEXP * s;
    }
}

extern "C" void kernel_launch(void* const* d_in, const int* in_sizes, int n_in,
                              void* d_out, int out_size) {
    const float* x  = (const float*)d_in[0];   // [B,T,D]
    const float* gw = (const float*)d_in[1];   // [D,E]
    const float* w1 = (const float*)d_in[2];   // [E,D,H]
    const float* w2 = (const float*)d_in[3];   // [E,H,D]
    float* out = (float*)d_out;

    cudaFuncSetAttribute(mma_gemm<1>, cudaFuncAttributeMaxDynamicSharedMemorySize, DYN1);
    cudaFuncSetAttribute(mma_gemm<2>, cudaFuncAttributeMaxDynamicSharedMemorySize, DYN2);

    zero_kernel<<<1, 32>>>();
    zero_out_kernel<<<(unsigned)((OUT_SZ / 4 + 255) / 256), 256>>>(out);
    router_kernel<<<(NTOK * 32) / 256, 256>>>(x, gw, out);
    scan_kernel<<<1, 32>>>();

    mma_gemm<1><<<dim3(HDIM / 128, NTOK / 128, NEXP), 256, DYN1>>>(x, w1, out);
    mma_gemm<2><<<dim3(DDIM / 128, NTOK / 128, NEXP), 256, DYN2>>>(nullptr, w2, out);

    aux_kernel<<<1, 32>>>(out);
}

// round 17
// speedup vs baseline: 1.1954x; 1.0254x over previous
// =============================================================================
// Round 17 theory (comments only, ASCII).
//
// Post-mortem R16: PASS, delta=0, 1308.9us (new best). The wide 64x32 warp
// tile recovered most of R4's GEMM efficiency while keeping the 64.3 MiB
// global footprint that passes reproducibly (3/3 now). Prediction was
// 950-1100; the ~200us shortfall matches the unhidden-gmem-latency model:
// the 2-stage pipeline waits on cp.async with only ONE k-tile in flight, and
// R4's profile (same shape) showed issue=28-34%, occ=11.9%, tensor=23-28% --
// stalls on long_scoreboard, not issue slots. R15 already proved the loop is
// not issue-bound at the margin.
//
// This round: ONE change -- deepen the pipeline to 4 STAGES with fully
// COMPILE-TIME buffer indexing (the R13 3-stage attempt died because
// runtime-indexed stage arrays spilled to local memory; here every stage id
// is a literal: prologue fills bufs 0-2, the mainloop is a by-4 unrolled
// block where each position names its buffer constant, and the 4-iter tail
// is written out explicitly with wait_group 2/2/1/0). Per iteration:
// wait_group 2 -> ONE syncthreads -> prefetch tile i+3 into the buffer
// freed at tile i-1 (safe: every thread passed that compute before this
// sync) -> compute tile i. Three k-tiles in flight instead of one, and one
// sync per iter instead of two.
// smem: stage1 4*(18432+17408)=140 KiB, stage2 108 KiB (max dyn smem 227 KiB
// on sm_100; occupancy stays 1 CTA/SM -- it already was at 167 regs).
//
// Prediction: PASS, delta=0 (globals unchanged, no runtime-indexed arrays),
// rel_err 4.2e-4 (bit-identical math), dur_us 1309 -> ~1050-1150 (GEMM
// scoreboard stalls cut by ~3x deeper prefetch + sync count halved). If the
// delta is small, the bottleneck is LDS/cvt ILP and the next lever is
// swapping the B operand path to fp16 smem tiles.
// =============================================================================
#include <cuda_runtime.h>
#include <cuda_fp16.h>
#include <math.h>
#include <stdint.h>

#define NTOK   8192
#define DDIM   1024
#define NEXP   8
#define HDIM   2048
#define NPAIR  (NTOK * 2)

#define OUT_OFF   ((size_t)0)
#define OUT_SZ    ((size_t)NTOK * DDIM)
#define AUX_OFF   (OUT_OFF + OUT_SZ)
#define PROBS_OFF (AUX_OFF + 1)
#define IDX_OFF   (PROBS_OFF + (size_t)NTOK * NEXP)
#define TP_OFF    (IDX_OFF + (size_t)NTOK * 2)

// ---- device scratch: 64.3 MiB total (identical to the passing builds) ----
__device__ __half g_h[(size_t)NPAIR * HDIM];   // 64 MiB, expert-sorted hidden
__device__ int    g_list[NEXP * NTOK];         // pid = tok*2+slot per expert
__device__ int    g_count[NEXP];
__device__ int    g_off[NEXP];
__device__ float  g_probsum[NEXP];

__device__ __forceinline__ float gelu_exact(float v) {
    return 0.5f * v * (1.0f + erff(v * 0.70710678118654752f));
}
__device__ __forceinline__ uint32_t tf32u(float v) {
    uint32_t r;
    asm("cvt.rna.tf32.f32 %0, %1;" : "=r"(r) : "f"(v));
    return r;
}
__device__ __forceinline__ uint32_t s2u(const void* p) {
    uint32_t a;
    asm("{ .reg .u64 t; cvta.to.shared.u64 t, %1; cvt.u32.u64 %0, t; }"
        : "=r"(a) : "l"(p));
    return a;
}
__device__ __forceinline__ void cpa16(uint32_t dst, const void* src) {
    asm volatile("cp.async.cg.shared.global [%0], [%1], 16;"
                 :: "r"(dst), "l"(src) : "memory");
}
#define CP_COMMIT() asm volatile("cp.async.commit_group;" ::: "memory")
#define CP_WAIT(N_) asm volatile("cp.async.wait_group %0;" :: "n"(N_) : "memory")

__device__ __forceinline__ void mma_tf32(
    float& c0, float& c1, float& c2, float& c3,
    uint32_t a0, uint32_t a1, uint32_t a2, uint32_t a3,
    uint32_t b0, uint32_t b1)
{
    asm volatile(
        "mma.sync.aligned.m16n8k8.row.col.f32.tf32.tf32.f32 "
        "{%0,%1,%2,%3}, {%4,%5,%6,%7}, {%8,%9}, {%0,%1,%2,%3};"
        : "+f"(c0), "+f"(c1), "+f"(c2), "+f"(c3)
        : "r"(a0), "r"(a1), "r"(a2), "r"(a3), "r"(b0), "r"(b1));
}

__global__ void zero_kernel() {
    int t = threadIdx.x;
    if (t < NEXP) { g_count[t] = 0; g_probsum[t] = 0.f; }
}

__global__ __launch_bounds__(256) void zero_out_kernel(float* __restrict__ out) {
    size_t i = (size_t)blockIdx.x * blockDim.x + threadIdx.x;
    if (i < OUT_SZ / 4)
        ((float4*)(out + OUT_OFF))[i] = make_float4(0.f, 0.f, 0.f, 0.f);
}

__global__ void scan_kernel() {
    if (threadIdx.x == 0) {
        int a = 0;
        for (int e = 0; e < NEXP; e++) { g_off[e] = a; a += g_count[e]; }
    }
}

__global__ __launch_bounds__(256) void router_kernel(
    const float* __restrict__ x, const float* __restrict__ gw,
    float* __restrict__ out)
{
    __shared__ float sprob[NEXP];
    int tid = threadIdx.x;
    if (tid < NEXP) sprob[tid] = 0.f;
    __syncthreads();

    int tok  = (blockIdx.x * blockDim.x + tid) >> 5;
    int lane = tid & 31;

    if (tok < NTOK) {
        const float* xr = x + (size_t)tok * DDIM;
        float acc[NEXP];
#pragma unroll
        for (int e = 0; e < NEXP; e++) acc[e] = 0.f;
        for (int d = lane; d < DDIM; d += 32) {
            float xv = xr[d];
            const float* g = gw + (size_t)d * NEXP;
#pragma unroll
            for (int e = 0; e < NEXP; e++) acc[e] += xv * g[e];
        }
#pragma unroll
        for (int off = 16; off > 0; off >>= 1)
#pragma unroll
            for (int e = 0; e < NEXP; e++)
                acc[e] += __shfl_down_sync(0xffffffffu, acc[e], off);

        if (lane == 0) {
            float mx = acc[0];
#pragma unroll
            for (int e = 1; e < NEXP; e++) mx = fmaxf(mx, acc[e]);
            float p[NEXP], s = 0.f;
#pragma unroll
            for (int e = 0; e < NEXP; e++) { p[e] = __expf(acc[e] - mx); s += p[e]; }
            float inv = 1.f / s;
#pragma unroll
            for (int e = 0; e < NEXP; e++) {
                p[e] *= inv;
                out[PROBS_OFF + (size_t)tok * NEXP + e] = p[e];
                atomicAdd(&sprob[e], p[e]);
            }
            int i0 = 0;
#pragma unroll
            for (int e = 1; e < NEXP; e++) if (p[e] > p[i0]) i0 = e;
            int i1 = -1;
#pragma unroll
            for (int e = 0; e < NEXP; e++)
                if (e != i0 && (i1 < 0 || p[e] > p[i1])) i1 = e;
            float ps  = p[i0] + p[i1];
            out[IDX_OFF + (size_t)tok * 2 + 0] = (float)i0;
            out[IDX_OFF + (size_t)tok * 2 + 1] = (float)i1;
            out[TP_OFF  + (size_t)tok * 2 + 0] = p[i0] / ps;
            out[TP_OFF  + (size_t)tok * 2 + 1] = p[i1] / ps;
            int pos0 = atomicAdd(&g_count[i0], 1);
            g_list[i0 * NTOK + pos0] = tok * 2 + 0;
            int pos1 = atomicAdd(&g_count[i1], 1);
            g_list[i1 * NTOK + pos1] = tok * 2 + 1;
        }
    }
    __syncthreads();
    if (tid < NEXP) atomicAdd(&g_probsum[tid], sprob[tid]);
}

// Grouped GEMM, tf32 mma.sync, CTA 128(M) x 128(N) x 32(K), 8 warps (2x4),
// warp tile 64x32 (acc[4][4][4], R4/R16 geometry). 4-STAGE cp.async pipeline
// with compile-time buffer ids only. B from UNtransposed weights, N-major
// smem [32][136], tf32 cvt at fragment load.
// STAGE 1: A = x rows gathered (cvt in-register), B = w1[e] -> g_h fp16
// STAGE 2: A = g_h sorted (fp16, exact in tf32), B = w2[e] -> atomicAdd out
#define BK    32
#define LDA1  36                        // floats
#define LDA2  40                        // halves
#define LDB   136                       // floats (128 cols + pad 8)
#define ATB1  (128 * LDA1 * 4)          // 18432 bytes
#define ATB2  (128 * LDA2 * 2)          // 10240 bytes
#define BTB   (BK * LDB * 4)            // 17408 bytes
#define DYN1  (4 * (ATB1 + BTB))        // 143360 bytes
#define DYN2  (4 * (ATB2 + BTB))        // 110592 bytes

template <int STAGE>
__global__ __launch_bounds__(256) void mma_gemm(
    const float* __restrict__ Xf, const float* __restrict__ W,
    float* __restrict__ out)
{
    constexpr int KD   = (STAGE == 1) ? DDIM : HDIM;
    constexpr int ND   = (STAGE == 1) ? HDIM : DDIM;
    constexpr int NIT  = KD / BK;           // 32 or 64, divisible by 4
    constexpr int ATB  = (STAGE == 1) ? ATB1 : ATB2;

    int e    = blockIdx.z;
    int cnt  = g_count[e];
    int row0 = blockIdx.y * 128;
    if (row0 >= cnt) return;
    int col0 = blockIdx.x * 128;
    int base = g_off[e];

    extern __shared__ __align__(16) char dyn[];
    uint32_t sb = s2u(dyn);

    int tid  = threadIdx.x;
    int wid  = tid >> 5;
    int lane = tid & 31;
    int g    = lane >> 2;
    int tg   = lane & 3;
    int wm   = (wid >> 2) * 64;   // 2 warp-rows cover M=128
    int wn   = (wid & 3) * 32;    // 4 warp-cols cover N=128

    // ---- load roles ----
    int lrow = tid >> 1;               // 0..127 (A row)
    const float*  arowF = nullptr;
    const __half* arowH = nullptr;
    if (STAGE == 1) {
        int m = row0 + lrow;
        int pid = (m < cnt) ? g_list[e * NTOK + m] : g_list[e * NTOK];
        arowF = Xf + (size_t)(pid >> 1) * DDIM + (tid & 1) * 16;
    } else {
        int m = row0 + lrow;
        size_t r = (m < cnt) ? (size_t)(base + m) : (size_t)base;
        arowH = g_h + r * HDIM + (tid & 1) * 16;
    }
    uint32_t aOff = (STAGE == 1)
        ? (uint32_t)(lrow * LDA1 + (tid & 1) * 16) * 4
        : (uint32_t)(lrow * LDA2 + (tid & 1) * 16) * 2;

    const float* wb = W + (size_t)e * DDIM * HDIM;
    int brow = tid >> 5;               // 0..7
    int bcol = (tid & 31) * 4;
    uint32_t bOff = (uint32_t)(brow * LDB + bcol) * 4;

    float acc[4][4][4];
#pragma unroll
    for (int i = 0; i < 4; i++)
#pragma unroll
        for (int j = 0; j < 4; j++)
#pragma unroll
            for (int c = 0; c < 4; c++) acc[i][j][c] = 0.f;

    // prefetch one k-tile into stage buffer S (S is always a literal)
    auto prefetch = [&](uint32_t aBase, uint32_t bBase, int kt) {
        if (STAGE == 1) {
#pragma unroll
            for (int j = 0; j < 4; j++)
                cpa16(aBase + aOff + j * 16, arowF + kt + j * 4);
        } else {
#pragma unroll
            for (int j = 0; j < 2; j++)
                cpa16(aBase + aOff + j * 16, arowH + kt + j * 8);
        }
#pragma unroll
        for (int j = 0; j < 4; j++)
            cpa16(bBase + bOff + j * (8 * LDB * 4),
                  wb + (size_t)(kt + brow + j * 8) * ND + col0 + bcol);
        CP_COMMIT();
    };

    auto compute = [&](const char* aBuf, const char* bBuf) {
        const float*  AtF = (const float*)aBuf;
        const __half* AtH = (const __half*)aBuf;
        const float*  Bt  = (const float*)bBuf;
#pragma unroll
        for (int kk = 0; kk < BK; kk += 8) {
            uint32_t bf[4][2];
#pragma unroll
            for (int ni = 0; ni < 4; ni++) {
                const float* bp = Bt + (kk + tg) * LDB + wn + ni * 8 + g;
                bf[ni][0] = tf32u(bp[0]);
                bf[ni][1] = tf32u(bp[4 * LDB]);
            }
#pragma unroll
            for (int mi = 0; mi < 4; mi++) {
                uint32_t a0, a1, a2, a3;
                if (STAGE == 1) {
                    const float* ap = AtF + (wm + mi * 16 + g) * LDA1 + kk + tg;
                    a0 = tf32u(ap[0]);
                    a1 = tf32u(ap[8 * LDA1]);
                    a2 = tf32u(ap[4]);
                    a3 = tf32u(ap[8 * LDA1 + 4]);
                } else {
                    // fp16 values are exactly tf32-representable
                    const __half* ap = AtH + (wm + mi * 16 + g) * LDA2 + kk + tg;
                    a0 = __float_as_uint(__half2float(ap[0]));
                    a1 = __float_as_uint(__half2float(ap[8 * LDA2]));
                    a2 = __float_as_uint(__half2float(ap[4]));
                    a3 = __float_as_uint(__half2float(ap[8 * LDA2 + 4]));
                }
#pragma unroll
                for (int ni = 0; ni < 4; ni++)
                    mma_tf32(acc[mi][ni][0], acc[mi][ni][1],
                             acc[mi][ni][2], acc[mi][ni][3],
                             a0, a1, a2, a3, bf[ni][0], bf[ni][1]);
            }
        }
    };

    // buffer base addresses (all literal-stage arithmetic, no arrays)
    const uint32_t aB0 = sb,            aB1 = sb + ATB;
    const uint32_t aB2 = sb + 2u * ATB, aB3 = sb + 3u * ATB;
    const uint32_t bBase = sb + 4u * ATB;
    const uint32_t bB0 = bBase,            bB1 = bBase + BTB;
    const uint32_t bB2 = bBase + 2u * BTB, bB3 = bBase + 3u * BTB;
    const char* aP0 = dyn;            const char* aP1 = dyn + ATB;
    const char* aP2 = dyn + 2 * ATB;  const char* aP3 = dyn + 3 * ATB;
    const char* bP0 = dyn + 4 * ATB;          const char* bP1 = dyn + 4 * ATB + BTB;
    const char* bP2 = dyn + 4 * ATB + 2 * BTB; const char* bP3 = dyn + 4 * ATB + 3 * BTB;

    // ---- prologue: tiles 0,1,2 into buffers 0,1,2 ----
    prefetch(aB0, bB0, 0);
    prefetch(aB1, bB1, BK);
    prefetch(aB2, bB2, 2 * BK);

    // ---- main: blocks of 4 iters, all with prefetch (tiles bt+3..bt+6) ----
    for (int bt = 0; bt + 8 <= NIT; bt += 4) {
        CP_WAIT(2); __syncthreads();
        prefetch(aB3, bB3, (bt + 3) * BK);
        compute(aP0, bP0);

        CP_WAIT(2); __syncthreads();
        prefetch(aB0, bB0, (bt + 4) * BK);
        compute(aP1, bP1);

        CP_WAIT(2); __syncthreads();
        prefetch(aB1, bB1, (bt + 5) * BK);
        compute(aP2, bP2);

        CP_WAIT(2); __syncthreads();
        prefetch(aB2, bB2, (bt + 6) * BK);
        compute(aP3, bP3);
    }

    // ---- tail block: tiles NIT-4..NIT-1 ----
    CP_WAIT(2); __syncthreads();
    prefetch(aB3, bB3, (NIT - 1) * BK);
    compute(aP0, bP0);

    CP_WAIT(2); __syncthreads();
    compute(aP1, bP1);

    CP_WAIT(1); __syncthreads();
    compute(aP2, bP2);

    CP_WAIT(0); __syncthreads();
    compute(aP3, bP3);

    // ---- epilogue ----
#pragma unroll
    for (int mi = 0; mi < 4; mi++) {
        int r0 = wm + mi * 16 + g;
        int r1 = r0 + 8;
        bool ok0 = (row0 + r0) < cnt;
        bool ok1 = (row0 + r1) < cnt;
        if (STAGE == 1) {
            __half* p0 = g_h + (size_t)(base + row0 + r0) * HDIM + col0;
            __half* p1 = g_h + (size_t)(base + row0 + r1) * HDIM + col0;
#pragma unroll
            for (int ni = 0; ni < 4; ni++) {
                int c = wn + ni * 8 + tg * 2;
                if (ok0) *(__half2*)(p0 + c) = __floats2half2_rn(
                    gelu_exact(acc[mi][ni][0]), gelu_exact(acc[mi][ni][1]));
                if (ok1) *(__half2*)(p1 + c) = __floats2half2_rn(
                    gelu_exact(acc[mi][ni][2]), gelu_exact(acc[mi][ni][3]));
            }
        } else {
            int pid0 = ok0 ? g_list[e * NTOK + row0 + r0] : 0;
            int pid1 = ok1 ? g_list[e * NTOK + row0 + r1] : 0;
            float w0v = ok0 ? out[TP_OFF + pid0] : 0.f;
            float w1v = ok1 ? out[TP_OFF + pid1] : 0.f;
            float* o0 = out + OUT_OFF + (size_t)(pid0 >> 1) * DDIM + col0;
            float* o1 = out + OUT_OFF + (size_t)(pid1 >> 1) * DDIM + col0;
#pragma unroll
            for (int ni = 0; ni < 4; ni++) {
                int c = wn + ni * 8 + tg * 2;
                if (ok0) {
                    atomicAdd(o0 + c,     w0v * acc[mi][ni][0]);
                    atomicAdd(o0 + c + 1, w0v * acc[mi][ni][1]);
                }
                if (ok1) {
                    atomicAdd(o1 + c,     w1v * acc[mi][ni][2]);
                    atomicAdd(o1 + c + 1, w1v * acc[mi][ni][3]);
                }
            }
        }
    }
}

__global__ void aux_kernel(float* __restrict__ out) {
    if (threadIdx.x == 0) {
        float s = 0.f;
#pragma unroll
        for (int e = 0; e < NEXP; e++)
            s += ((float)g_count[e] / (float)NTOK) * (g_probsum[e] / (float)NTOK);
        out[AUX_OFF] = (float)NEXP * s;
    }
}

extern "C" void kernel_launch(void* const* d_in, const int* in_sizes, int n_in,
                              void* d_out, int out_size) {
    const float* x  = (const float*)d_in[0];   // [B,T,D]
    const float* gw = (const float*)d_in[1];   // [D,E]
    const float* w1 = (const float*)d_in[2];   // [E,D,H]
    const float* w2 = (const float*)d_in[3];   // [E,H,D]
    float* out = (float*)d_out;

    cudaFuncSetAttribute(mma_gemm<1>, cudaFuncAttributeMaxDynamicSharedMemorySize, DYN1);
    cudaFuncSetAttribute(mma_gemm<2>, cudaFuncAttributeMaxDynamicSharedMemorySize, DYN2);

    zero_kernel<<<1, 32>>>();
    zero_out_kernel<<<(unsigned)((OUT_SZ / 4 + 255) / 256), 256>>>(out);
    router_kernel<<<(NTOK * 32) / 256, 256>>>(x, gw, out);
    scan_kernel<<<1, 32>>>();

    mma_gemm<1><<<dim3(HDIM / 128, NTOK / 128, NEXP), 256, DYN1>>>(x, w1, out);
    mma_gemm<2><<<dim3(DDIM / 128, NTOK / 128, NEXP), 256, DYN2>>>(nullptr, w2, out);

    aux_kernel<<<1, 32>>>(out);
}